// round 3
// baseline (speedup 1.0000x reference)
#include <cuda_runtime.h>
#include <math.h>

#define BB 8
#define TT 2560
#define FF 229
#define C1 5
#define C2 11
#define F2 114
#define F3 57
#define FEAT 627
#define OFT 88
#define MCC 48
#define GG 8
#define DH 6
#define KK 31
#define PADW 15
#define TP (TT + 2*PADW)      /* 2590 */
#define KPAD 640
#define NROW (BB*TT)          /* 20480 */
#define BNEPS 1e-5f

typedef unsigned long long u64;

__device__ __forceinline__ u64 f2pack(float lo, float hi) {
    u64 r; asm("mov.b64 %0,{%1,%2};" : "=l"(r) : "f"(lo), "f"(hi)); return r;
}
__device__ __forceinline__ u64 ffma2(u64 a, u64 b, u64 c) {
    u64 d; asm("fma.rn.f32x2 %0,%1,%2,%3;" : "=l"(d) : "l"(a), "l"(b), "l"(c)); return d;
}
__device__ __forceinline__ float2 f2unpack(u64 v) {
    float2 r; asm("mov.b64 {%0,%1},%2;" : "=f"(r.x), "=f"(r.y) : "l"(v)); return r;
}

// ---- scratch (device globals: allocation-free) ----
__device__ float g_buf1[(long)BB*TT*FF*8];   // conv1 out, NHWC, ch padded to 8
__device__ float g_buf2[(long)BB*TT*F2*8];   // conv2+pool out, ch padded to 8
__device__ float g_buf3[(long)NROW*FEAT];    // conv3+pool out, feature vec (c*57+f)
__device__ float g_Wc[3*KPAD*48];            // fused fc+qkv weights, k-major [sec][k][48]
__device__ float g_bc[144];
__device__ float g_q[(long)NROW*MCC];
__device__ float g_k[(long)BB*TP*MCC];       // padded along T
__device__ float g_v[(long)BB*TP*MCC];

// ------------------------------------------------------------------
// conv1: 1->5 ch, 3x3 SAME, BN, ReLU (packed f32x2 over co pairs)
// ------------------------------------------------------------------
__global__ void __launch_bounds__(256) k_conv1(
        const float* __restrict__ spec, const float* __restrict__ w,
        const float* __restrict__ cb, const float* __restrict__ bg,
        const float* __restrict__ bb, const float* __restrict__ bm,
        const float* __restrict__ bv) {
    __shared__ u64 wp[9*3];           // [tap][cop]
    __shared__ float sA[C1], sD[C1];
    int tid = threadIdx.x;
    if (tid < 27) {
        int cop = tid % 3, tap = tid / 3;
        int co0 = 2*cop, co1 = co0 + 1;
        float w0 = w[co0*9 + tap];
        float w1 = (co1 < C1) ? w[co1*9 + tap] : 0.f;
        wp[tap*3 + cop] = f2pack(w0, w1);
    }
    if (tid < C1) {
        float s = bg[tid] * rsqrtf(bv[tid] + BNEPS);
        sA[tid] = s;
        sD[tid] = (cb[tid] - bm[tid]) * s + bb[tid];
    }
    __syncthreads();
    long idx = (long)blockIdx.x * blockDim.x + tid;
    if (idx >= (long)BB*TT*FF) return;
    int f = (int)(idx % FF);
    int t = (int)((idx / FF) % TT);
    int b = (int)(idx / ((long)FF*TT));
    u64 pp[3][3];
#pragma unroll
    for (int ky = 0; ky < 3; ky++) {
        int tt2 = t - 1 + ky;
#pragma unroll
        for (int kx = 0; kx < 3; kx++) {
            int ff = f - 1 + kx;
            float val = 0.f;
            if (tt2 >= 0 && tt2 < TT && ff >= 0 && ff < FF)
                val = spec[((long)b*TT + tt2)*FF + ff];
            pp[ky][kx] = f2pack(val, val);
        }
    }
    u64 acc[3] = {0ull, 0ull, 0ull};
#pragma unroll
    for (int tap = 0; tap < 9; tap++)
#pragma unroll
        for (int cop = 0; cop < 3; cop++)
            acc[cop] = ffma2(pp[tap/3][tap%3], wp[tap*3 + cop], acc[cop]);

    float y[6];
#pragma unroll
    for (int cop = 0; cop < 3; cop++) {
        float2 a = f2unpack(acc[cop]);
        int c0 = 2*cop, c1 = c0 + 1;
        y[c0] = fmaxf(fmaf(a.x, sA[c0], sD[c0]), 0.f);
        y[c1] = (c1 < C1) ? fmaxf(fmaf(a.y, sA[c1], sD[c1]), 0.f) : 0.f;
    }
    float4* o = (float4*)&g_buf1[idx * 8];
    o[0] = make_float4(y[0], y[1], y[2], y[3]);
    o[1] = make_float4(y[4], 0.f, 0.f, 0.f);
}

// ------------------------------------------------------------------
// conv2: 5->5 ch, 3x3 SAME, BN, ReLU, maxpool W (229->114)
// packed f32x2 over co pairs; both pooled cols share weight loads
// ------------------------------------------------------------------
__global__ void __launch_bounds__(256) k_conv2(
        const float* __restrict__ w, const float* __restrict__ cb,
        const float* __restrict__ bg, const float* __restrict__ bb,
        const float* __restrict__ bm, const float* __restrict__ bv) {
    __shared__ u64 wp[5*3*3*3];       // [ci][ky][kx][cop]
    __shared__ float sA[C1], sD[C1];
    int tid = threadIdx.x;
    for (int i = tid; i < 135; i += blockDim.x) {
        int cop = i % 3, kx = (i/3) % 3, ky = (i/9) % 3, ci = i/27;
        int co0 = 2*cop, co1 = co0 + 1;
        float w0 = w[(co0*C1 + ci)*9 + ky*3 + kx];
        float w1 = (co1 < C1) ? w[(co1*C1 + ci)*9 + ky*3 + kx] : 0.f;
        wp[((ci*3 + ky)*3 + kx)*3 + cop] = f2pack(w0, w1);
    }
    if (tid < C1) {
        float s = bg[tid] * rsqrtf(bv[tid] + BNEPS);
        sA[tid] = s;
        sD[tid] = (cb[tid] - bm[tid]) * s + bb[tid];
    }
    __syncthreads();
    long idx = (long)blockIdx.x * blockDim.x + tid;
    if (idx >= (long)BB*TT*F2) return;
    int f2 = (int)(idx % F2);
    int t  = (int)((idx / F2) % TT);
    int b  = (int)(idx / ((long)F2*TT));
    u64 acc[2][3];
#pragma unroll
    for (int p = 0; p < 2; p++)
#pragma unroll
        for (int c = 0; c < 3; c++) acc[p][c] = 0ull;

#pragma unroll
    for (int ky = 0; ky < 3; ky++) {
        int tt2 = t - 1 + ky;
        u64 pc[4][C1];
        if (tt2 >= 0 && tt2 < TT) {
            const float* rowbase = &g_buf1[((long)b*TT + tt2) * FF * 8];
#pragma unroll
            for (int cx = 0; cx < 4; cx++) {
                int ff = 2*f2 - 1 + cx;
                if (ff >= 0 && ff < FF) {
                    float4 v4 = *(const float4*)(rowbase + (long)ff*8);
                    float v5 = rowbase[(long)ff*8 + 4];
                    pc[cx][0] = f2pack(v4.x, v4.x);
                    pc[cx][1] = f2pack(v4.y, v4.y);
                    pc[cx][2] = f2pack(v4.z, v4.z);
                    pc[cx][3] = f2pack(v4.w, v4.w);
                    pc[cx][4] = f2pack(v5, v5);
                } else {
#pragma unroll
                    for (int ci = 0; ci < C1; ci++) pc[cx][ci] = 0ull;
                }
            }
        } else {
#pragma unroll
            for (int cx = 0; cx < 4; cx++)
#pragma unroll
                for (int ci = 0; ci < C1; ci++) pc[cx][ci] = 0ull;
        }
#pragma unroll
        for (int kx = 0; kx < 3; kx++)
#pragma unroll
            for (int cop = 0; cop < 3; cop++)
#pragma unroll
                for (int ci = 0; ci < C1; ci++) {
                    u64 wv = wp[((ci*3 + ky)*3 + kx)*3 + cop];
                    acc[0][cop] = ffma2(pc[kx][ci],   wv, acc[0][cop]);
                    acc[1][cop] = ffma2(pc[kx+1][ci], wv, acc[1][cop]);
                }
    }
    float* o = &g_buf2[idx * 8];
#pragma unroll
    for (int cop = 0; cop < 3; cop++) {
        float2 a0 = f2unpack(acc[0][cop]);
        float2 a1 = f2unpack(acc[1][cop]);
        int c0 = 2*cop, c1 = c0 + 1;
        float y0 = fmaxf(fmaf(a0.x, sA[c0], sD[c0]), 0.f);
        float y1 = fmaxf(fmaf(a1.x, sA[c0], sD[c0]), 0.f);
        o[c0] = fmaxf(y0, y1);
        if (c1 < C1) {
            float z0 = fmaxf(fmaf(a0.y, sA[c1], sD[c1]), 0.f);
            float z1 = fmaxf(fmaf(a1.y, sA[c1], sD[c1]), 0.f);
            o[c1] = fmaxf(z0, z1);
        }
    }
}

// ------------------------------------------------------------------
// conv3: 5->11 ch, 3x3 SAME, BN, ReLU, maxpool W (114->57)
// ------------------------------------------------------------------
__global__ void __launch_bounds__(256) k_conv3(
        const float* __restrict__ w, const float* __restrict__ cb,
        const float* __restrict__ bg, const float* __restrict__ bb,
        const float* __restrict__ bm, const float* __restrict__ bv) {
    __shared__ u64 wp[5*3*3*6];       // [ci][ky][kx][cop]
    __shared__ float sA[C2], sD[C2];
    int tid = threadIdx.x;
    for (int i = tid; i < 270; i += blockDim.x) {
        int cop = i % 6, kx = (i/6) % 3, ky = (i/18) % 3, ci = i/54;
        int co0 = 2*cop, co1 = co0 + 1;
        float w0 = w[(co0*C1 + ci)*9 + ky*3 + kx];
        float w1 = (co1 < C2) ? w[(co1*C1 + ci)*9 + ky*3 + kx] : 0.f;
        wp[((ci*3 + ky)*3 + kx)*6 + cop] = f2pack(w0, w1);
    }
    if (tid < C2) {
        float s = bg[tid] * rsqrtf(bv[tid] + BNEPS);
        sA[tid] = s;
        sD[tid] = (cb[tid] - bm[tid]) * s + bb[tid];
    }
    __syncthreads();
    long idx = (long)blockIdx.x * blockDim.x + tid;
    if (idx >= (long)BB*TT*F3) return;
    int f2 = (int)(idx % F3);
    int t  = (int)((idx / F3) % TT);
    int b  = (int)(idx / ((long)F3*TT));
    u64 acc[2][6];
#pragma unroll
    for (int p = 0; p < 2; p++)
#pragma unroll
        for (int c = 0; c < 6; c++) acc[p][c] = 0ull;

#pragma unroll
    for (int ky = 0; ky < 3; ky++) {
        int tt2 = t - 1 + ky;
        u64 pc[4][C1];
        if (tt2 >= 0 && tt2 < TT) {
            const float* rowbase = &g_buf2[((long)b*TT + tt2) * F2 * 8];
#pragma unroll
            for (int cx = 0; cx < 4; cx++) {
                int ff = 2*f2 - 1 + cx;
                if (ff >= 0 && ff < F2) {
                    float4 v4 = *(const float4*)(rowbase + (long)ff*8);
                    float v5 = rowbase[(long)ff*8 + 4];
                    pc[cx][0] = f2pack(v4.x, v4.x);
                    pc[cx][1] = f2pack(v4.y, v4.y);
                    pc[cx][2] = f2pack(v4.z, v4.z);
                    pc[cx][3] = f2pack(v4.w, v4.w);
                    pc[cx][4] = f2pack(v5, v5);
                } else {
#pragma unroll
                    for (int ci = 0; ci < C1; ci++) pc[cx][ci] = 0ull;
                }
            }
        } else {
#pragma unroll
            for (int cx = 0; cx < 4; cx++)
#pragma unroll
                for (int ci = 0; ci < C1; ci++) pc[cx][ci] = 0ull;
        }
#pragma unroll
        for (int kx = 0; kx < 3; kx++)
#pragma unroll
            for (int cop = 0; cop < 6; cop++)
#pragma unroll
                for (int ci = 0; ci < C1; ci++) {
                    u64 wv = wp[((ci*3 + ky)*3 + kx)*6 + cop];
                    acc[0][cop] = ffma2(pc[kx][ci],   wv, acc[0][cop]);
                    acc[1][cop] = ffma2(pc[kx+1][ci], wv, acc[1][cop]);
                }
    }
    float* o = &g_buf3[((long)b*TT + t) * FEAT];
#pragma unroll
    for (int cop = 0; cop < 6; cop++) {
        float2 a0 = f2unpack(acc[0][cop]);
        float2 a1 = f2unpack(acc[1][cop]);
        int c0 = 2*cop, c1 = c0 + 1;
        float y0 = fmaxf(fmaf(a0.x, sA[c0], sD[c0]), 0.f);
        float y1 = fmaxf(fmaf(a1.x, sA[c0], sD[c0]), 0.f);
        o[c0*F3 + f2] = fmaxf(y0, y1);
        if (c1 < C2) {
            float z0 = fmaxf(fmaf(a0.y, sA[c1], sD[c1]), 0.f);
            float z1 = fmaxf(fmaf(a1.y, sA[c1], sD[c1]), 0.f);
            o[c1*F3 + f2] = fmaxf(z0, z1);
        }
    }
}

// ------------------------------------------------------------------
// fold fc into q/k/v, k-major layout: g_Wc[(sec*KPAD + k)*48 + r]
// ------------------------------------------------------------------
__global__ void k_combine(const float* __restrict__ wq, const float* __restrict__ wk,
                          const float* __restrict__ wv, const float* __restrict__ fcw,
                          const float* __restrict__ fcb) {
    int id = blockIdx.x * blockDim.x + threadIdx.x;
    if (id >= 3*KPAD*48) return;
    int r = id % 48;
    int k = (id / 48) % KPAD;
    int sec = id / (KPAD*48);
    const float* wsel = (sec == 0) ? (wq + r*OFT) : (sec == 1) ? (wk + r*OFT) : (wv + r*OFT);
    float acc = 0.f;
    if (k < FEAT) {
        for (int m = 0; m < OFT; m++) acc = fmaf(wsel[m], fcw[(long)m*FEAT + k], acc);
    }
    g_Wc[id] = acc;
    if (k == 0) {
        float bacc = 0.f;
        for (int m = 0; m < OFT; m++) bacc = fmaf(wsel[m], fcb[m], bacc);
        g_bc[sec*48 + r] = bacc;
    }
}

// zero the T-pad rows of k/v
__global__ void k_padzero() {
    int idx = blockIdx.x * blockDim.x + threadIdx.x;
    int total = BB * 2*PADW * MCC;
    if (idx >= total) return;
    int c = idx % MCC;
    int r = (idx / MCC) % (2*PADW);
    int b = idx / (MCC * 2*PADW);
    int tp = (r < PADW) ? r : (TT + PADW + (r - PADW));
    g_k[((long)b*TP + tp)*MCC + c] = 0.f;
    g_v[((long)b*TP + tp)*MCC + c] = 0.f;
}

// ------------------------------------------------------------------
// QKV GEMM: (20480 x 627) @ (627 x 48) per section (q,k,v via blockIdx.y)
// 64x48 tile, 256 threads, packed f32x2 over column pairs
// thread: tx(8) -> 3 col-pairs, ty(32) -> 2 rows
// ------------------------------------------------------------------
__global__ void __launch_bounds__(256) k_qkv() {
    __shared__ float Xs[64][33];
    __shared__ u64 Wp[32*24];         // [kk][colpair]
    int tid = threadIdx.x;
    int sec = blockIdx.y;
    int row0 = blockIdx.x * 64;
    int tx = tid & 7, ty = tid >> 3;
    u64 acc[2][3];
#pragma unroll
    for (int i = 0; i < 2; i++)
#pragma unroll
        for (int j = 0; j < 3; j++) acc[i][j] = 0ull;

    for (int k0 = 0; k0 < FEAT; k0 += 32) {
#pragma unroll
        for (int i = 0; i < 8; i++) {
            int e = tid + 256*i;
            int r = e >> 5, c = e & 31;
            int kk = k0 + c;
            Xs[r][c] = (kk < FEAT) ? g_buf3[(long)(row0 + r)*FEAT + kk] : 0.f;
        }
#pragma unroll
        for (int i = 0; i < 3; i++) {
            int e = tid + 256*i;
            int kk = e / 24, cp = e % 24;
            float2 v = *(const float2*)&g_Wc[((long)sec*KPAD + k0 + kk)*48 + cp*2];
            Wp[kk*24 + cp] = f2pack(v.x, v.y);
        }
        __syncthreads();
#pragma unroll
        for (int kk = 0; kk < 32; kk++) {
            float a0 = Xs[ty*2+0][kk];
            float a1 = Xs[ty*2+1][kk];
            u64 pa0 = f2pack(a0, a0);
            u64 pa1 = f2pack(a1, a1);
#pragma unroll
            for (int j = 0; j < 3; j++) {
                u64 bv = Wp[kk*24 + tx*3 + j];
                acc[0][j] = ffma2(pa0, bv, acc[0][j]);
                acc[1][j] = ffma2(pa1, bv, acc[1][j]);
            }
        }
        __syncthreads();
    }
#pragma unroll
    for (int rp = 0; rp < 2; rp++) {
        int row = row0 + ty*2 + rp;
        int b = row / TT, t = row % TT;
#pragma unroll
        for (int j = 0; j < 3; j++) {
            int cp = tx*3 + j;
            float2 a = f2unpack(acc[rp][j]);
            a.x += g_bc[sec*48 + 2*cp];
            a.y += g_bc[sec*48 + 2*cp + 1];
            if (sec == 0) {
                *(float2*)&g_q[(long)row*MCC + 2*cp] = a;
            } else {
                float* dst = (sec == 1) ? g_k : g_v;
                *(float2*)&dst[((long)b*TP + t + PADW)*MCC + 2*cp] = a;
            }
        }
    }
}

// ------------------------------------------------------------------
// fused attention + LN + linear + sigmoid; one warp per (b,t)
// ------------------------------------------------------------------
__global__ void k_attn(const float* __restrict__ rel, const float* __restrict__ lng,
                       const float* __restrict__ lnb, const float* __restrict__ linw,
                       const float* __restrict__ linb, float* __restrict__ out) {
    __shared__ float s_rel[MCC*KK];
    __shared__ float s_linw[OFT*MCC];
    __shared__ float s_linb[OFT];
    __shared__ float s_lng[MCC], s_lnb[MCC];
    __shared__ float s_q[8][MCC];
    __shared__ float s_attn[8][GG][KK+1];
    __shared__ float s_h[8][MCC];
    int tid = threadIdx.x;
    for (int i = tid; i < MCC*KK; i += 256) s_rel[i] = rel[i];
    for (int i = tid; i < OFT*MCC; i += 256) s_linw[i] = linw[i];
    if (tid < OFT) s_linb[tid] = linb[tid];
    if (tid < MCC) { s_lng[tid] = lng[tid]; s_lnb[tid] = lnb[tid]; }
    __syncthreads();

    int wid = tid >> 5, lane = tid & 31;
    int bt = blockIdx.x * 8 + wid;
    int b = bt / TT, t = bt % TT;

    s_q[wid][lane] = g_q[(long)bt*MCC + lane];
    if (lane < 16) s_q[wid][lane + 32] = g_q[(long)bt*MCC + lane + 32];
    __syncwarp();

    int j = lane;
    float e[GG];
    if (j < KK) {
        const float* kr = &g_k[((long)b*TP + t + j)*MCC];
#pragma unroll
        for (int g = 0; g < GG; g++) {
            float s = 0.f;
#pragma unroll
            for (int d = 0; d < DH; d++) {
                int c = g*DH + d;
                s = fmaf(s_q[wid][c], kr[c] + s_rel[c*KK + j], s);
            }
            e[g] = s;
        }
    } else {
#pragma unroll
        for (int g = 0; g < GG; g++) e[g] = -INFINITY;
    }

    long aoff = (long)NROW*OFT + (long)bt*GG*KK;
#pragma unroll
    for (int g = 0; g < GG; g++) {
        float m = e[g];
#pragma unroll
        for (int o = 16; o; o >>= 1) m = fmaxf(m, __shfl_xor_sync(0xffffffffu, m, o));
        float p = (j < KK) ? __expf(e[g] - m) : 0.f;
        float s = p;
#pragma unroll
        for (int o = 16; o; o >>= 1) s += __shfl_xor_sync(0xffffffffu, s, o);
        float a = p / s;
        if (j < KK) {
            s_attn[wid][g][j] = a;
            out[aoff + g*KK + j] = a;
        }
    }
    __syncwarp();

    int c1 = lane;
    int c2 = lane + 32;
    int g1 = c1 / DH;
    float o1 = 0.f, o2 = 0.f;
    const float* vbase = &g_v[((long)b*TP + t)*MCC];
#pragma unroll
    for (int jj = 0; jj < KK; jj++) {
        const float* vr = vbase + (long)jj*MCC;
        o1 = fmaf(s_attn[wid][g1][jj], vr[c1], o1);
        if (lane < 16) {
            int g2 = c2 / DH;
            o2 = fmaf(s_attn[wid][g2][jj], vr[c2], o2);
        }
    }

    float lsum = o1 + ((lane < 16) ? o2 : 0.f);
    float lsq  = o1*o1 + ((lane < 16) ? o2*o2 : 0.f);
#pragma unroll
    for (int o = 16; o; o >>= 1) {
        lsum += __shfl_xor_sync(0xffffffffu, lsum, o);
        lsq  += __shfl_xor_sync(0xffffffffu, lsq,  o);
    }
    float mu = lsum * (1.f/48.f);
    float var = lsq * (1.f/48.f) - mu*mu;
    float inv = rsqrtf(var + 1e-5f);
    s_h[wid][c1] = (o1 - mu)*inv*s_lng[c1] + s_lnb[c1];
    if (lane < 16) s_h[wid][c2] = (o2 - mu)*inv*s_lng[c2] + s_lnb[c2];
    __syncwarp();

#pragma unroll
    for (int rr = 0; rr < 3; rr++) {
        int o = lane + rr*32;
        if (o < OFT) {
            float s = s_linb[o];
#pragma unroll
            for (int c = 0; c < MCC; c++)
                s = fmaf(s_h[wid][c], s_linw[o*MCC + c], s);
            out[(long)bt*OFT + o] = 1.f / (1.f + __expf(-s));
        }
    }
}

// ------------------------------------------------------------------
extern "C" void kernel_launch(void* const* d_in, const int* in_sizes, int n_in,
                              void* d_out, int out_size) {
    const float* spec = (const float*)d_in[0];
    const float* c1w  = (const float*)d_in[1];
    const float* c1b  = (const float*)d_in[2];
    const float* bn1g = (const float*)d_in[3];
    const float* bn1b = (const float*)d_in[4];
    const float* bn1m = (const float*)d_in[5];
    const float* bn1v = (const float*)d_in[6];
    const float* c2w  = (const float*)d_in[7];
    const float* c2b  = (const float*)d_in[8];
    const float* bn2g = (const float*)d_in[9];
    const float* bn2b = (const float*)d_in[10];
    const float* bn2m = (const float*)d_in[11];
    const float* bn2v = (const float*)d_in[12];
    const float* c3w  = (const float*)d_in[13];
    const float* c3b  = (const float*)d_in[14];
    const float* bn3g = (const float*)d_in[15];
    const float* bn3b = (const float*)d_in[16];
    const float* bn3m = (const float*)d_in[17];
    const float* bn3v = (const float*)d_in[18];
    const float* fcw  = (const float*)d_in[19];
    const float* fcb  = (const float*)d_in[20];
    const float* wq   = (const float*)d_in[21];
    const float* wk   = (const float*)d_in[22];
    const float* wv   = (const float*)d_in[23];
    const float* rel  = (const float*)d_in[24];
    const float* lng  = (const float*)d_in[25];
    const float* lnb  = (const float*)d_in[26];
    const float* linw = (const float*)d_in[27];
    const float* linb = (const float*)d_in[28];
    float* out = (float*)d_out;

    k_conv1<<<(BB*TT*FF + 255)/256, 256>>>(spec, c1w, c1b, bn1g, bn1b, bn1m, bn1v);
    k_conv2<<<(BB*TT*F2 + 255)/256, 256>>>(c2w, c2b, bn2g, bn2b, bn2m, bn2v);
    k_conv3<<<(BB*TT*F3 + 255)/256, 256>>>(c3w, c3b, bn3g, bn3b, bn3m, bn3v);
    k_combine<<<(3*KPAD*48 + 255)/256, 256>>>(wq, wk, wv, fcw, fcb);
    k_padzero<<<(BB*2*PADW*MCC + 255)/256, 256>>>();
    {
        dim3 grid(NROW/64, 3);
        k_qkv<<<grid, 256>>>();
    }
    k_attn<<<NROW/8, 256>>>(rel, lng, lnb, linw, linb, out);
}